// round 9
// baseline (speedup 1.0000x reference)
#include <cuda_runtime.h>
#include <cstddef>

#define T_STEPS 8192
#define NRES    2048
#define DIN     64
#define DOUT    64
#define GBLK    128          // CTAs; 16 rows each
#define TPB     256
#define LEAK    0.3f
#define NOISE_L 0.01f
#define TILE_T  128

// ---------------- scratch (device globals: allocation-free) ----------------
__device__ float    g_drive [T_STEPS * NRES];   // 64 MB
__device__ float    g_states[T_STEPS * NRES];   // 64 MB
__device__ float    g_sbuf  [2][NRES];          // double-buffered reservoir state
__device__ unsigned g_ctrs[8 * 32];             // 8 group counters, 128B apart

// ---------------- kernel 0: reset counters + state (determinism) ------------
__global__ void init_kernel() {
    int i = blockIdx.x * blockDim.x + threadIdx.x;
    if (i < NRES) { g_sbuf[0][i] = 0.f; g_sbuf[1][i] = 0.f; }
    if (i < 8 * 32) g_ctrs[i] = 0u;
}

// ---------------- kernel 1: drive = u @ W_in^T + 0.01*noise -----------------
__global__ void drive_kernel(const float* __restrict__ u,
                             const float* __restrict__ noise,
                             const float* __restrict__ W_in) {
    __shared__ float4 u_sh[TILE_T * (DIN / 4)];
    const int n  = blockIdx.x * 256 + threadIdx.x;
    const int t0 = blockIdx.y * TILE_T;

    float4 w[DIN / 4];
    const float4* Wv = reinterpret_cast<const float4*>(W_in);
    #pragma unroll
    for (int j = 0; j < DIN / 4; j++) w[j] = Wv[(size_t)n * (DIN / 4) + j];

    const float4* uv = reinterpret_cast<const float4*>(u + (size_t)t0 * DIN);
    for (int i = threadIdx.x; i < TILE_T * (DIN / 4); i += 256) u_sh[i] = uv[i];
    __syncthreads();

    for (int t = 0; t < TILE_T; t++) {
        float acc = 0.f;
        #pragma unroll
        for (int j = 0; j < DIN / 4; j++) {
            float4 uu = u_sh[t * (DIN / 4) + j];
            acc += w[j].x * uu.x + w[j].y * uu.y + w[j].z * uu.z + w[j].w * uu.w;
        }
        size_t idx = (size_t)(t0 + t) * NRES + n;
        g_drive[idx] = acc + NOISE_L * noise[idx];
    }
}

// ---------------- kernel 2: persistent reservoir, group-pipelined -----------
// Warp w consumes state group w (cols 256w..256w+255), produced by CTAs
// 16w..16w+15. Per-group counters let each warp start its matvec as soon as
// ITS producers finish — skew overlaps with compute instead of serializing.
__global__ void __launch_bounds__(TPB, 1) reservoir_kernel(const float* __restrict__ W) {
    __shared__ float red_sh[2][8][17];        // parity-buffered warp partials

    const int tid  = threadIdx.x;
    const int cta  = blockIdx.x;
    const int warp = tid >> 5;
    const int lane = tid & 31;
    const int row  = lane & 15;               // local row 0..15 (partial owner)
    const int half = lane >> 4;               // 0: cols +0..127, 1: +128..255
    const int grow = cta * 16 + row;          // global row of my partial

    // W slice: row grow, cols [warp*256 + half*128, +128) -> 64 f32x2 regs
    const int c0 = warp * 256 + half * 128;
    const float4* Wv = reinterpret_cast<const float4*>(W + (size_t)grow * NRES + c0);
    unsigned long long wp[64];
    #pragma unroll
    for (int k = 0; k < 32; k++) {
        float4 a = Wv[k];
        wp[2*k]   = ((unsigned long long)__float_as_uint(a.y) << 32) | __float_as_uint(a.x);
        wp[2*k+1] = ((unsigned long long)__float_as_uint(a.w) << 32) | __float_as_uint(a.z);
    }

    // Distributed tail: warp w finalizes rows 2w (lane 0) and 2w+1 (lane 8)
    const bool fin    = (lane == 0) || (lane == 8);
    const int  frow   = cta * 16 + warp * 2 + (lane >> 3);   // lane0->2w, lane8->2w+1
    float sp   = 0.f;
    float dcur = 0.f;
    if (fin) dcur = g_drive[frow];

    unsigned* myctr = &g_ctrs[warp * 32];     // this warp's group counter
    const int f4base = warp * 64 + half * 32; // float4 idx of my 128 cols

    #pragma unroll 1
    for (int t = 0; t < T_STEPS; t++) {
        // ---- wait for MY group's producers only ---------------------------
        const unsigned target = (unsigned)t * 128u;   // 16 CTAs x 8 warps per step
        unsigned c;
        do {
            asm volatile("ld.acquire.gpu.global.u32 %0, [%1];"
                         : "=r"(c) : "l"(myctr));
        } while (c < target);

        // ---- matvec partial: direct L2 reads (lane-broadcast dedup) -------
        const float4* s4 = reinterpret_cast<const float4*>(g_sbuf[t & 1]) + f4base;
        unsigned long long aA = 0, aB = 0, aC = 0, aD = 0;
        #pragma unroll
        for (int k = 0; k < 32; k += 2) {
            float4 sv  = __ldcg(s4 + k);
            float4 sv2 = __ldcg(s4 + k + 1);
            asm("{\n\t"
                ".reg .b64 p0, p1, p2, p3;\n\t"
                "mov.b64 p0, {%4, %5};\n\t"
                "mov.b64 p1, {%6, %7};\n\t"
                "mov.b64 p2, {%8, %9};\n\t"
                "mov.b64 p3, {%10, %11};\n\t"
                "fma.rn.f32x2 %0, %12, p0, %0;\n\t"
                "fma.rn.f32x2 %1, %13, p1, %1;\n\t"
                "fma.rn.f32x2 %2, %14, p2, %2;\n\t"
                "fma.rn.f32x2 %3, %15, p3, %3;\n\t"
                "}"
                : "+l"(aA), "+l"(aB), "+l"(aC), "+l"(aD)
                : "f"(sv.x), "f"(sv.y), "f"(sv.z), "f"(sv.w),
                  "f"(sv2.x), "f"(sv2.y), "f"(sv2.z), "f"(sv2.w),
                  "l"(wp[2*k]), "l"(wp[2*k+1]), "l"(wp[2*k+2]), "l"(wp[2*k+3]));
        }
        float e0, o0, e1, o1;
        asm("{\n\t.reg .b64 r0;\n\tadd.rn.f32x2 r0, %2, %3;\n\tmov.b64 {%0, %1}, r0;\n\t}"
            : "=f"(e0), "=f"(o0) : "l"(aA), "l"(aB));
        asm("{\n\t.reg .b64 r1;\n\tadd.rn.f32x2 r1, %2, %3;\n\tmov.b64 {%0, %1}, r1;\n\t}"
            : "=f"(e1), "=f"(o1) : "l"(aC), "l"(aD));
        float part = (e0 + o0) + (e1 + o1);
        part += __shfl_xor_sync(0xffffffffu, part, 16);    // combine halves

        const int par = t & 1;
        if (lane < 16) red_sh[par][warp][row] = part;
        __syncthreads();                                   // the ONLY CTA barrier

        // ---- distributed tail: warp w finalizes rows 2w, 2w+1 -------------
        // lanes 0-7 carry row 2w partials, lanes 8-15 row 2w+1
        float p = 0.f;
        if (lane < 16) {
            int srcw = lane & 7;
            int r    = warp * 2 + (lane >> 3);
            p = red_sh[par][srcw][r];
        }
        p += __shfl_xor_sync(0xffffffffu, p, 4);
        p += __shfl_xor_sync(0xffffffffu, p, 2);
        p += __shfl_xor_sync(0xffffffffu, p, 1);
        // lanes 0 and 8 now hold full sums for their rows

        if (fin) {
            float x  = dcur + p;
            float z  = __expf(2.f * x);                    // tanh = 1 - 2/(e^2x+1)
            float th = 1.f - __fdividef(2.f, z + 1.f);
            float ns = (1.f - LEAK) * sp + LEAK * th;
            sp = ns;
            g_sbuf[(t + 1) & 1][frow] = ns;
            __stcs(&g_states[(size_t)t * NRES + frow], ns);
            if (t + 1 < T_STEPS)                           // prefetch under spin
                dcur = g_drive[(size_t)(t + 1) * NRES + frow];
        }
        __syncwarp();                                      // order both row stores
        if (lane == 0)
            asm volatile("red.release.gpu.global.add.u32 [%0], 1;"
                         :: "l"(&g_ctrs[(cta >> 4) * 32]) : "memory");
        // no trailing CTA barrier: red_sh is parity-buffered, and the next
        // bar orders tail reads (t) before any STS (t+2) reuse.
    }
}

// ---------------- kernel 3: out = states @ w_out^T + b_out ------------------
__global__ void proj_kernel(const float* __restrict__ w_out,
                            const float* __restrict__ b_out,
                            float* __restrict__ out) {
    __shared__ float s_sh[32][33];
    __shared__ float w_sh[DOUT][33];
    const int t0  = blockIdx.x * 32;
    const int tid = threadIdx.x;
    const int tx  = tid & 15;
    const int ty  = tid >> 4;
    float acc[2][4] = {};

    for (int kc = 0; kc < NRES; kc += 32) {
        for (int i = tid; i < 32 * 32; i += 256) {
            int r = i >> 5, k = i & 31;
            s_sh[r][k] = g_states[(size_t)(t0 + r) * NRES + kc + k];
        }
        for (int i = tid; i < DOUT * 32; i += 256) {
            int o = i >> 5, k = i & 31;
            w_sh[o][k] = w_out[(size_t)o * NRES + kc + k];
        }
        __syncthreads();
        for (int k = 0; k < 32; k++) {
            float sv[2], wv[4];
            #pragma unroll
            for (int i = 0; i < 2; i++) sv[i] = s_sh[ty * 2 + i][k];
            #pragma unroll
            for (int j = 0; j < 4; j++) wv[j] = w_sh[tx * 4 + j][k];
            #pragma unroll
            for (int i = 0; i < 2; i++)
                #pragma unroll
                for (int j = 0; j < 4; j++)
                    acc[i][j] += sv[i] * wv[j];
        }
        __syncthreads();
    }
    #pragma unroll
    for (int i = 0; i < 2; i++)
        #pragma unroll
        for (int j = 0; j < 4; j++)
            out[(size_t)(t0 + ty * 2 + i) * DOUT + tx * 4 + j] = acc[i][j] + b_out[tx * 4 + j];
}

// ---------------- launch ----------------------------------------------------
extern "C" void kernel_launch(void* const* d_in, const int* in_sizes, int n_in,
                              void* d_out, int out_size) {
    const float* u     = (const float*)d_in[0];  // (8192, 64)
    const float* noise = (const float*)d_in[1];  // (8192, 2048)
    const float* W_in  = (const float*)d_in[2];  // (2048, 64)
    const float* W     = (const float*)d_in[3];  // (2048, 2048)
    const float* w_out = (const float*)d_in[4];  // (64, 2048)
    const float* b_out = (const float*)d_in[5];  // (64,)
    float* out = (float*)d_out;                  // (8192, 64)

    init_kernel<<<NRES / 256, 256>>>();
    drive_kernel<<<dim3(NRES / 256, T_STEPS / TILE_T), 256>>>(u, noise, W_in);
    reservoir_kernel<<<GBLK, TPB>>>(W);
    proj_kernel<<<T_STEPS / 32, 256>>>(w_out, b_out, out);
}

// round 10
// speedup vs baseline: 1.4844x; 1.4844x over previous
#include <cuda_runtime.h>
#include <cstddef>
#include <cstdio>

#define T_STEPS 8192
#define NRES    2048
#define DIN     64
#define DOUT    64
#define GBLK    128          // CTAs; 16 rows each (RF-forced: W lives in registers)
#define TPB     256
#define LEAK    0.3f
#define NOISE_L 0.01f
#define TILE_T  128

// ---------------- scratch (device globals: allocation-free) ----------------
__device__ float    g_drive [T_STEPS * NRES];   // 64 MB
__device__ float    g_states[T_STEPS * NRES];   // 64 MB
__device__ float    g_sbuf  [2][NRES];          // double-buffered reservoir state
__device__ unsigned g_ctr;                      // monotonic barrier counter
__device__ unsigned long long g_prof[8];        // phase-cycle accumulators

// ---------------- kernel 0: reset barrier + state (determinism) -------------
__global__ void init_kernel() {
    int i = blockIdx.x * blockDim.x + threadIdx.x;
    if (i < NRES) { g_sbuf[0][i] = 0.f; g_sbuf[1][i] = 0.f; }
    if (i == 0) g_ctr = 0u;
    if (i < 8) g_prof[i] = 0ull;
}

// ---------------- kernel 1: drive = u @ W_in^T + 0.01*noise -----------------
__global__ void drive_kernel(const float* __restrict__ u,
                             const float* __restrict__ noise,
                             const float* __restrict__ W_in) {
    __shared__ float4 u_sh[TILE_T * (DIN / 4)];
    const int n  = blockIdx.x * 256 + threadIdx.x;
    const int t0 = blockIdx.y * TILE_T;

    float4 w[DIN / 4];
    const float4* Wv = reinterpret_cast<const float4*>(W_in);
    #pragma unroll
    for (int j = 0; j < DIN / 4; j++) w[j] = Wv[(size_t)n * (DIN / 4) + j];

    const float4* uv = reinterpret_cast<const float4*>(u + (size_t)t0 * DIN);
    for (int i = threadIdx.x; i < TILE_T * (DIN / 4); i += 256) u_sh[i] = uv[i];
    __syncthreads();

    for (int t = 0; t < TILE_T; t++) {
        float acc = 0.f;
        #pragma unroll
        for (int j = 0; j < DIN / 4; j++) {
            float4 uu = u_sh[t * (DIN / 4) + j];
            acc += w[j].x * uu.x + w[j].y * uu.y + w[j].z * uu.z + w[j].w * uu.w;
        }
        size_t idx = (size_t)(t0 + t) * NRES + n;
        g_drive[idx] = acc + NOISE_L * noise[idx];
    }
}

// ---------------- kernel 2: persistent reservoir (R7 structure) -------------
// Counter barrier (release-red / acquire-ld), single coalesced staging sweep,
// f32x2 FMAs, fast tanh, dual publisher lanes. Instrumented with clock64.
__global__ void __launch_bounds__(TPB, 1) reservoir_kernel(const float* __restrict__ W) {
    __shared__ float s_sh[NRES];              // 8 KB staged state

    const int tid  = threadIdx.x;
    const int cta  = blockIdx.x;
    const int warp = tid >> 5;
    const int lane = tid & 31;
    const int r0   = cta * 16 + warp * 2;

    // One-time: load W slice, pack column pairs into 64-bit (f32x2) registers
    const float4* Wv = reinterpret_cast<const float4*>(W);
    unsigned long long w0[32], w1[32];
    #pragma unroll
    for (int j = 0; j < 16; j++) {
        float4 a = Wv[(size_t)r0 * (NRES / 4) + lane + 32 * j];
        float4 b = Wv[(size_t)(r0 + 1) * (NRES / 4) + lane + 32 * j];
        w0[2*j]   = ((unsigned long long)__float_as_uint(a.y) << 32) | __float_as_uint(a.x);
        w0[2*j+1] = ((unsigned long long)__float_as_uint(a.w) << 32) | __float_as_uint(a.z);
        w1[2*j]   = ((unsigned long long)__float_as_uint(b.y) << 32) | __float_as_uint(b.x);
        w1[2*j+1] = ((unsigned long long)__float_as_uint(b.w) << 32) | __float_as_uint(b.z);
    }

    const bool pub   = (lane & 15) == 0;      // lanes 0 and 16 publish
    const int  myrow = r0 + (lane >> 4);      // lane0 -> r0, lane16 -> r0+1
    float sp   = 0.f;                         // own row's previous state
    float dcur = 0.f;
    if (pub) dcur = g_drive[myrow];           // drive at t=0

    unsigned long long aStage = 0, aComp = 0, aTail = 0, aWait = 0, aRel = 0;

    #pragma unroll 1
    for (int t = 0; t < T_STEPS; t++) {
        unsigned long long c0 = clock64();

        // ---- stage s(t): ONE coalesced L1-bypassing sweep ------------------
        const float4* sin = reinterpret_cast<const float4*>(g_sbuf[t & 1]);
        float4 v0 = __ldcg(&sin[tid]);
        float4 v1 = __ldcg(&sin[tid + 256]);
        reinterpret_cast<float4*>(s_sh)[tid]       = v0;
        reinterpret_cast<float4*>(s_sh)[tid + 256] = v1;
        // off-critical-path: write OUR rows of states[t-1] from staged data
        // (s_sh will hold s(t) = states[t-1]'s successor; the value staged here
        //  IS states[t-1] for rows we own -> write from the freshly read regs)
        // rows owned: warp's 2 rows live in s_sh[r0], s_sh[r0+1]; simpler:
        // publisher lanes stored them last step; here lanes<16 of warp 0 write
        // the CTA's 16 rows of the PREVIOUS state from global staging regs.
        if (t > 0 && warp == 0 && lane < 16) {
            // previous state value for global row cta*16+lane:
            float pv = __ldca(&g_sbuf[t & 1][cta * 16 + lane]);  // L1 hit; just read
            g_states[(size_t)(t - 1) * NRES + cta * 16 + lane] = pv;
        }
        __syncthreads();                      // bar A
        unsigned long long c1 = clock64();

        // ---- packed f32x2 mat-vec partials ---------------------------------
        const float4* s4 = reinterpret_cast<const float4*>(s_sh);
        unsigned long long acc0a = 0, acc0b = 0, acc1a = 0, acc1b = 0;
        #pragma unroll
        for (int j = 0; j < 16; j++) {
            float4 sv = s4[lane + 32 * j];
            asm("{\n\t"
                ".reg .b64 sA, sB;\n\t"
                "mov.b64 sA, {%4, %5};\n\t"
                "mov.b64 sB, {%6, %7};\n\t"
                "fma.rn.f32x2 %0, %8, sA, %0;\n\t"
                "fma.rn.f32x2 %1, %9, sB, %1;\n\t"
                "fma.rn.f32x2 %2, %10, sA, %2;\n\t"
                "fma.rn.f32x2 %3, %11, sB, %3;\n\t"
                "}"
                : "+l"(acc0a), "+l"(acc0b), "+l"(acc1a), "+l"(acc1b)
                : "f"(sv.x), "f"(sv.y), "f"(sv.z), "f"(sv.w),
                  "l"(w0[2*j]), "l"(w0[2*j+1]), "l"(w1[2*j]), "l"(w1[2*j+1]));
        }
        float e0, o0, e1, o1;
        asm("{\n\t.reg .b64 t0r;\n\tadd.rn.f32x2 t0r, %2, %3;\n\tmov.b64 {%0, %1}, t0r;\n\t}"
            : "=f"(e0), "=f"(o0) : "l"(acc0a), "l"(acc0b));
        asm("{\n\t.reg .b64 t1r;\n\tadd.rn.f32x2 t1r, %2, %3;\n\tmov.b64 {%0, %1}, t1r;\n\t}"
            : "=f"(e1), "=f"(o1) : "l"(acc1a), "l"(acc1b));
        float acc0 = e0 + o0;
        float acc1 = e1 + o1;
        #pragma unroll
        for (int off = 16; off > 0; off >>= 1) {
            acc0 += __shfl_xor_sync(0xffffffffu, acc0, off);
            acc1 += __shfl_xor_sync(0xffffffffu, acc1, off);
        }
        unsigned long long c2 = clock64();

        // ---- update + publish (2 parallel chains per warp) -----------------
        float dnext = dcur;
        if (pub) {
            float a  = (lane < 16) ? acc0 : acc1;
            float x  = dcur + a;
            float z  = __expf(2.f * x);                   // tanh = 1 - 2/(e^2x+1)
            float th = 1.f - __fdividef(2.f, z + 1.f);
            float ns = (1.f - LEAK) * sp + LEAK * th;
            sp = ns;
            g_sbuf[(t + 1) & 1][myrow] = ns;              // release via red below
            if (t == T_STEPS - 1)                         // last state: no next stage
                g_states[(size_t)t * NRES + myrow] = ns;
            if (t + 1 < T_STEPS)                          // prefetch under spin
                dnext = g_drive[(size_t)(t + 1) * NRES + myrow];
        }
        __syncthreads();                      // bar C: all stores precede arrival
        unsigned long long c3 = clock64();

        // ---- monotonic grid barrier (release-red / acquire-ld) -------------
        if (tid == 0) {
            asm volatile("red.release.gpu.global.add.u32 [%0], 1;"
                         :: "l"(&g_ctr) : "memory");
            const unsigned target = (unsigned)(t + 1) * GBLK;
            unsigned c;
            do {
                asm volatile("ld.acquire.gpu.global.u32 %0, [%1];"
                             : "=r"(c) : "l"(&g_ctr));
            } while (c < target);
        }
        unsigned long long c4 = clock64();
        __syncthreads();                      // bar D: release CTA
        unsigned long long c5 = clock64();

        aStage += c1 - c0; aComp += c2 - c1; aTail += c3 - c2;
        aWait  += c4 - c3; aRel  += c5 - c4;
        dcur = dnext;
    }

    if (cta == 0 && tid == 0) {
        g_prof[0] = aStage; g_prof[1] = aComp; g_prof[2] = aTail;
        g_prof[3] = aWait;  g_prof[4] = aRel;
        g_prof[5] = aStage + aComp + aTail + aWait + aRel;
    }
}

// ---------------- kernel 2b: dump per-step phase cycles to stdout -----------
__global__ void prof_print_kernel() {
    printf("PROF cyc/step: stage=%llu comp=%llu tail=%llu wait=%llu rel=%llu total=%llu\n",
           g_prof[0] / T_STEPS, g_prof[1] / T_STEPS, g_prof[2] / T_STEPS,
           g_prof[3] / T_STEPS, g_prof[4] / T_STEPS, g_prof[5] / T_STEPS);
}

// ---------------- kernel 3: out = states @ w_out^T + b_out ------------------
__global__ void proj_kernel(const float* __restrict__ w_out,
                            const float* __restrict__ b_out,
                            float* __restrict__ out) {
    __shared__ float s_sh[32][33];
    __shared__ float w_sh[DOUT][33];
    const int t0  = blockIdx.x * 32;
    const int tid = threadIdx.x;
    const int tx  = tid & 15;
    const int ty  = tid >> 4;
    float acc[2][4] = {};

    for (int kc = 0; kc < NRES; kc += 32) {
        for (int i = tid; i < 32 * 32; i += 256) {
            int r = i >> 5, k = i & 31;
            s_sh[r][k] = g_states[(size_t)(t0 + r) * NRES + kc + k];
        }
        for (int i = tid; i < DOUT * 32; i += 256) {
            int o = i >> 5, k = i & 31;
            w_sh[o][k] = w_out[(size_t)o * NRES + kc + k];
        }
        __syncthreads();
        for (int k = 0; k < 32; k++) {
            float sv[2], wv[4];
            #pragma unroll
            for (int i = 0; i < 2; i++) sv[i] = s_sh[ty * 2 + i][k];
            #pragma unroll
            for (int j = 0; j < 4; j++) wv[j] = w_sh[tx * 4 + j][k];
            #pragma unroll
            for (int i = 0; i < 2; i++)
                #pragma unroll
                for (int j = 0; j < 4; j++)
                    acc[i][j] += sv[i] * wv[j];
        }
        __syncthreads();
    }
    #pragma unroll
    for (int i = 0; i < 2; i++)
        #pragma unroll
        for (int j = 0; j < 4; j++)
            out[(size_t)(t0 + ty * 2 + i) * DOUT + tx * 4 + j] = acc[i][j] + b_out[tx * 4 + j];
}

// ---------------- launch ----------------------------------------------------
extern "C" void kernel_launch(void* const* d_in, const int* in_sizes, int n_in,
                              void* d_out, int out_size) {
    const float* u     = (const float*)d_in[0];  // (8192, 64)
    const float* noise = (const float*)d_in[1];  // (8192, 2048)
    const float* W_in  = (const float*)d_in[2];  // (2048, 64)
    const float* W     = (const float*)d_in[3];  // (2048, 2048)
    const float* w_out = (const float*)d_in[4];  // (64, 2048)
    const float* b_out = (const float*)d_in[5];  // (64,)
    float* out = (float*)d_out;                  // (8192, 64)

    init_kernel<<<NRES / 256, 256>>>();
    drive_kernel<<<dim3(NRES / 256, T_STEPS / TILE_T), 256>>>(u, noise, W_in);
    reservoir_kernel<<<GBLK, TPB>>>(W);
    prof_print_kernel<<<1, 1>>>();
    proj_kernel<<<T_STEPS / 32, 256>>>(w_out, b_out, out);
}